// round 15
// baseline (speedup 1.0000x reference)
#include <cuda_runtime.h>

// SpatialShift: x (ns=128, m=12, t=784, c=64) fp32.
// ns = b*16 + h*4 + w (H=W=4, shift s=1). Channel d = m*64 + c, fold f=48.
//
// R15: R10's transport recipe (7-deep volatile front-batch, .cs both ways,
// tchunk-fastest grid) + SOURCE-CENTRIC diagonal groups: in groups 4..7,
// 5 of 16 cells were read twice (shift reader + identity-border reader),
// costing 24MB of duplicate DRAM reads that no cache policy recovers (R9).
// Each diagonal thread now loads its OWN cell once and stores it to up to
// two destinations (shifted dest if in-bounds; own position if the identity
// condition holds). Coverage of out is exact and write-once.
// DRAM traffic: 597 -> 573 MB (-4%).

// Packed delta tables: 2 bits per group g (0..8), value = delta + 1.
// dh: {+1,-1,0,0,-1,+1,-1,+1, 0}
// dw: { 0, 0,+1,-1,-1,+1,+1,-1, 0}
#define DH_PACK 100434u
#define DW_PACK 75813u

__device__ __forceinline__ float4 ldg_cs_v4(const float4* p) {
    float4 v;
    asm volatile("ld.global.cs.v4.f32 {%0,%1,%2,%3}, [%4];"
                 : "=f"(v.x), "=f"(v.y), "=f"(v.z), "=f"(v.w)
                 : "l"(p));
    return v;
}

__device__ __forceinline__ void stg_cs_v4(float4* p, float4 v) {
    asm volatile("st.global.cs.v4.f32 [%0], {%1,%2,%3,%4};"
                 :: "l"(p), "f"(v.x), "f"(v.y), "f"(v.z), "f"(v.w)
                 : "memory");
}

__global__ void __launch_bounds__(256)
spatial_shift_kernel(const float4* __restrict__ x, float4* __restrict__ out) {
    const int c4      = threadIdx.x & 15;   // float4 index within c (0..15)
    const int t_local = threadIdx.x >> 4;   // 0..15

    int blk = blockIdx.x;
    const int tchunk = blk % 7;   blk /= 7;    // 7 * 112 = 784 = t
    const int m      = blk % 12;  blk /= 12;
    const int ns     = blk;                    // 0..127

    const int h = (ns >> 2) & 3;
    const int w = ns & 3;

    const int d = m * 64 + c4 * 4;
    int g = d / 48;
    if (g > 8) g = 8;

    const int dh = (int)((DH_PACK >> (2 * g)) & 3u) - 1;
    const int dw = (int)((DW_PACK >> (2 * g)) & 3u) - 1;

    const int t0 = tchunk * 112 + t_local;
    // float4 index of (ns, m, t, c4): ((ns*12 + m)*784 + t)*16 + c4
    // max = 128*12*784*16 = 19,267,584 < 2^31 -> 32-bit offsets safe.
    const int base = ((ns * 12 + m) * 784 + t0) * 16 + c4;

    if (g >= 4 && g < 8) {
        // ---- source-centric diagonal: load own cell once, store 0..2x ----
        const int h1 = h - dh;                 // shifted destination
        const int w1 = w - dw;
        const bool s1 = ((unsigned)h1 <= 3u) && ((unsigned)w1 <= 3u);
        // identity-kept at own position iff own source (h+dh,w+dw) is OOB
        const bool s2 = ((unsigned)(h + dh) > 3u) || ((unsigned)(w + dw) > 3u);
        if (!s1 && !s2) return;                // cell never read (5/16 cells)

        const float4* s = x + base;
        float4 v[7];
#pragma unroll
        for (int i = 0; i < 7; i++)
            v[i] = ldg_cs_v4(s + i * 256);     // all 7 loads issue first

        if (s1) {
            const int ns1 = (ns & ~15) | (h1 << 2) | w1;
            float4* o1 = out + (base + (ns1 - ns) * 150528);
#pragma unroll
            for (int i = 0; i < 7; i++)
                stg_cs_v4(o1 + i * 256, v[i]);
        }
        if (s2) {
            float4* o2 = out + base;
#pragma unroll
            for (int i = 0; i < 7; i++)
                stg_cs_v4(o2 + i * 256, v[i]);
        }
        return;
    }

    // ---- axis groups (g<4) + identity tail (g==8): destination-centric ----
    float4* o = out + base;

    const int hs = h + dh;
    const int ws = w + dw;
    if (g < 4 && (((unsigned)hs > 3u) || ((unsigned)ws > 3u))) {
        const float4 z = make_float4(0.f, 0.f, 0.f, 0.f);
#pragma unroll
        for (int i = 0; i < 7; i++)
            stg_cs_v4(o + i * 256, z);
        return;
    }

    const int ns_src = (g < 4) ? ((ns & ~15) | (hs << 2) | ws) : ns;
    const float4* s = x + (base + (ns_src - ns) * 150528);

    float4 v[7];
#pragma unroll
    for (int i = 0; i < 7; i++)
        v[i] = ldg_cs_v4(s + i * 256);   // volatile asm: all 7 issue first

#pragma unroll
    for (int i = 0; i < 7; i++)
        stg_cs_v4(o + i * 256, v[i]);    // volatile asm: after all loads
}

extern "C" void kernel_launch(void* const* d_in, const int* in_sizes, int n_in,
                              void* d_out, int out_size) {
    const float4* x = (const float4*)d_in[0];
    float4* out = (float4*)d_out;
    // blocks = 128 * 12 * 7 = 10,752 ; 256 threads, 7 float4 each
    spatial_shift_kernel<<<10752, 256>>>(x, out);
}